// round 1
// baseline (speedup 1.0000x reference)
#include <cuda_runtime.h>
#include <math.h>

#define Nn 4096
#define Ee 65536
#define Dd 128
#define Tt 8192   // 2*Nn

// ---------------- scratch (static device allocations only) ----------------
__device__ float g_X[Tt * Dd];
__device__ float g_H[Tt * Dd];
__device__ float g_k[Tt * Dd];
__device__ float g_v[Tt * Dd];
__device__ float g_q[Tt * Dd];
__device__ float g_ao[Tt * Dd];
__device__ float g_feats[(size_t)Tt * 2 * Dd];
__device__ float g_agg[(size_t)Tt * 2 * Dd];
__device__ int   g_deg[Tt];

// ---------------- generic GEMM: C = act( [C +] A@B + bias ) ----------------
// A[M,K], B[K,N], C[M,N], row-major. M,N multiples of 64, K multiple of 16.
__global__ void gemm_kernel(const float* __restrict__ A, const float* __restrict__ B,
                            const float* __restrict__ bias, float* __restrict__ C,
                            int M, int N, int K, int accum, int relu)
{
    __shared__ float sA[64][20];  // [m][k], BK=16 padded to 20
    __shared__ float sB[16][64];  // [k][n]
    const int tid = threadIdx.x;
    const int tm = (tid >> 4) << 2;
    const int tn = (tid & 15) << 2;
    const int bm = blockIdx.x * 64;
    const int bn = blockIdx.y * 64;
    float acc[4][4] = {};

    for (int k0 = 0; k0 < K; k0 += 16) {
        {
            int r = tid >> 2;
            int c = (tid & 3) << 2;
            float4 av = *(const float4*)(A + (size_t)(bm + r) * K + k0 + c);
            *(float4*)&sA[r][c] = av;
        }
        {
            int rb = tid >> 4;
            int cb = (tid & 15) << 2;
            float4 bv = *(const float4*)(B + (size_t)(k0 + rb) * N + bn + cb);
            *(float4*)&sB[rb][cb] = bv;
        }
        __syncthreads();
        #pragma unroll
        for (int k = 0; k < 16; k++) {
            float a0 = sA[tm + 0][k], a1 = sA[tm + 1][k];
            float a2 = sA[tm + 2][k], a3 = sA[tm + 3][k];
            float4 b4 = *(float4*)&sB[k][tn];
            acc[0][0] += a0 * b4.x; acc[0][1] += a0 * b4.y; acc[0][2] += a0 * b4.z; acc[0][3] += a0 * b4.w;
            acc[1][0] += a1 * b4.x; acc[1][1] += a1 * b4.y; acc[1][2] += a1 * b4.z; acc[1][3] += a1 * b4.w;
            acc[2][0] += a2 * b4.x; acc[2][1] += a2 * b4.y; acc[2][2] += a2 * b4.z; acc[2][3] += a2 * b4.w;
            acc[3][0] += a3 * b4.x; acc[3][1] += a3 * b4.y; acc[3][2] += a3 * b4.z; acc[3][3] += a3 * b4.w;
        }
        __syncthreads();
    }

    float4 b4 = make_float4(0.f, 0.f, 0.f, 0.f);
    if (bias) b4 = *(const float4*)(bias + bn + tn);
    #pragma unroll
    for (int i = 0; i < 4; i++) {
        size_t off = (size_t)(bm + tm + i) * N + bn + tn;
        float4 v = make_float4(acc[i][0] + b4.x, acc[i][1] + b4.y,
                               acc[i][2] + b4.z, acc[i][3] + b4.w);
        if (accum) {
            float4 c4 = *(const float4*)(C + off);
            v.x += c4.x; v.y += c4.y; v.z += c4.z; v.w += c4.w;
        }
        if (relu) {
            v.x = fmaxf(v.x, 0.f); v.y = fmaxf(v.y, 0.f);
            v.z = fmaxf(v.z, 0.f); v.w = fmaxf(v.w, 0.f);
        }
        *(float4*)(C + off) = v;
    }
}

// ---------------- flash attention (fp32, online softmax) ----------------
// O[q] = sum_t softmax_t(K[t].Q[q] / sqrt(128)) * V[t];  Q rows per graph.
// grid: (Nn/64, 2 graphs), 256 threads.
#define ATTN_SMEM ((64 * 129 + 64 * 132 + 64 * 65) * 4)
__global__ void attn_kernel(const float* __restrict__ Q, const float* __restrict__ K,
                            const float* __restrict__ V, float* __restrict__ O)
{
    extern __shared__ float sm[];
    float* sQ  = sm;                 // 64 x (128+1)
    float* sKV = sm + 64 * 129;      // K: 64x129 (S stage) / V: 64x132 (accum stage)
    float* sS  = sKV + 64 * 132;     // 64 x 65
    const int tid = threadIdx.x;
    const int qbase = blockIdx.y * Nn + blockIdx.x * 64;

    for (int i = tid; i < 64 * 32; i += 256) {
        int r = i >> 5, c = (i & 31) << 2;
        float4 v4 = *(const float4*)(Q + (size_t)(qbase + r) * Dd + c);
        float* p = sQ + r * 129 + c;
        p[0] = v4.x; p[1] = v4.y; p[2] = v4.z; p[3] = v4.w;
    }

    const int tm = (tid >> 4) << 2;
    const int tn = (tid & 15) << 2;
    const int m  = tid & 63;
    const int db = (tid >> 6) << 5;   // 0,32,64,96
    const float inv_scale = 0.08838834764831845f;

    float4 acc[8];
    #pragma unroll
    for (int t = 0; t < 8; t++) acc[t] = make_float4(0.f, 0.f, 0.f, 0.f);
    float mrun = -1e30f, lrun = 0.f;
    __syncthreads();

    for (int n0 = 0; n0 < Tt; n0 += 64) {
        // K tile (pad 129)
        for (int i = tid; i < 64 * 32; i += 256) {
            int r = i >> 5, c = (i & 31) << 2;
            float4 v4 = *(const float4*)(K + (size_t)(n0 + r) * Dd + c);
            float* p = sKV + r * 129 + c;
            p[0] = v4.x; p[1] = v4.y; p[2] = v4.z; p[3] = v4.w;
        }
        __syncthreads();

        // S = Q.K^T (4x4 register tile)
        float s[4][4] = {};
        #pragma unroll 4
        for (int k = 0; k < Dd; k++) {
            float a0 = sQ[(tm + 0) * 129 + k], a1 = sQ[(tm + 1) * 129 + k];
            float a2 = sQ[(tm + 2) * 129 + k], a3 = sQ[(tm + 3) * 129 + k];
            float b0 = sKV[(tn + 0) * 129 + k], b1 = sKV[(tn + 1) * 129 + k];
            float b2 = sKV[(tn + 2) * 129 + k], b3 = sKV[(tn + 3) * 129 + k];
            s[0][0] += a0 * b0; s[0][1] += a0 * b1; s[0][2] += a0 * b2; s[0][3] += a0 * b3;
            s[1][0] += a1 * b0; s[1][1] += a1 * b1; s[1][2] += a1 * b2; s[1][3] += a1 * b3;
            s[2][0] += a2 * b0; s[2][1] += a2 * b1; s[2][2] += a2 * b2; s[2][3] += a2 * b3;
            s[3][0] += a3 * b0; s[3][1] += a3 * b1; s[3][2] += a3 * b2; s[3][3] += a3 * b3;
        }
        #pragma unroll
        for (int i = 0; i < 4; i++)
            #pragma unroll
            for (int j = 0; j < 4; j++)
                sS[(tm + i) * 65 + tn + j] = s[i][j] * inv_scale;
        __syncthreads();

        // V tile (pad 132, float4-aligned)
        for (int i = tid; i < 64 * 32; i += 256) {
            int r = i >> 5, c = (i & 31) << 2;
            *(float4*)(sKV + r * 132 + c) = *(const float4*)(V + (size_t)(n0 + r) * Dd + c);
        }
        __syncthreads();

        // online softmax + PV accumulate (thread owns query m, dims [db, db+32))
        float tmax = -1e30f;
        #pragma unroll 8
        for (int n = 0; n < 64; n++) tmax = fmaxf(tmax, sS[m * 65 + n]);
        float nm = fmaxf(mrun, tmax);
        float corr = __expf(mrun - nm);
        lrun *= corr;
        #pragma unroll
        for (int t = 0; t < 8; t++) {
            acc[t].x *= corr; acc[t].y *= corr; acc[t].z *= corr; acc[t].w *= corr;
        }
        for (int n = 0; n < 64; n++) {
            float p = __expf(sS[m * 65 + n] - nm);
            lrun += p;
            const float* vp = sKV + n * 132 + db;
            #pragma unroll
            for (int t = 0; t < 8; t++) {
                float4 v4 = *(const float4*)(vp + (t << 2));
                acc[t].x += p * v4.x; acc[t].y += p * v4.y;
                acc[t].z += p * v4.z; acc[t].w += p * v4.w;
            }
        }
        mrun = nm;
        __syncthreads();
    }

    float inv_l = 1.f / lrun;
    float* op = O + (size_t)(qbase + m) * Dd + db;
    #pragma unroll
    for (int t = 0; t < 8; t++) {
        float4 r = acc[t];
        r.x *= inv_l; r.y *= inv_l; r.z *= inv_l; r.w *= inv_l;
        *(float4*)(op + (t << 2)) = r;
    }
}

// ---------------- feats = [X | X - attn_out] ----------------
__global__ void feats_kernel(const float* __restrict__ X, const float* __restrict__ AO,
                             float* __restrict__ F)
{
    int i = blockIdx.x * blockDim.x + threadIdx.x;   // over Tt*32 float4s
    if (i >= Tt * 32) return;
    int r = i >> 5, c = i & 31;
    float4 x = ((const float4*)X)[(size_t)r * 32 + c];
    float4 o = ((const float4*)AO)[(size_t)r * 32 + c];
    ((float4*)F)[(size_t)r * 64 + c] = x;
    ((float4*)F)[(size_t)r * 64 + 32 + c] =
        make_float4(x.x - o.x, x.y - o.y, x.z - o.z, x.w - o.w);
}

// ---------------- edge scatter: segment-sum of feats[src] into agg[dst] ----------------
__global__ void edge_kernel(const int* __restrict__ ei1, const int* __restrict__ ei2,
                            const float* __restrict__ F, float* __restrict__ AGG,
                            int* __restrict__ DEG)
{
    const int g = blockIdx.y;
    const int* ei = g ? ei2 : ei1;
    const int base = g * Nn;
    for (int e = blockIdx.x; e < Ee; e += gridDim.x) {
        int src = ei[e] + base;
        int dst = ei[Ee + e] + base;
        atomicAdd(&AGG[(size_t)dst * 256 + threadIdx.x], F[(size_t)src * 256 + threadIdx.x]);
        if (threadIdx.x == 0) atomicAdd(&DEG[dst], 1);
    }
}

// ---------------- mean = agg / max(deg,1) ----------------
__global__ void mean_kernel(float* __restrict__ AGG, const int* __restrict__ DEG)
{
    int i = blockIdx.x * blockDim.x + threadIdx.x;   // over Tt*64 float4s
    if (i >= Tt * 64) return;
    int r = i >> 6;
    int d = DEG[r];
    float s = 1.f / (float)(d > 1 ? d : 1);
    float4 v = ((float4*)AGG)[i];
    v.x *= s; v.y *= s; v.z *= s; v.w *= s;
    ((float4*)AGG)[i] = v;
}

// ---------------- final: OUT = sigmoid(F @ F^T), F[8192,128] ----------------
__global__ void final_kernel(const float* __restrict__ F, float* __restrict__ OUT)
{
    __shared__ float sA[64][33];   // pad 33 -> <=2-way conflicts
    __shared__ float sB[64][33];
    const int tid = threadIdx.x;
    const int tm = (tid >> 4) << 2;
    const int tn = (tid & 15) << 2;
    const int bm = blockIdx.x * 64;
    const int bn = blockIdx.y * 64;
    float acc[4][4] = {};

    for (int k0 = 0; k0 < Dd; k0 += 32) {
        #pragma unroll
        for (int it = 0; it < 2; it++) {
            int i = tid + it * 256;
            int r = i >> 3, c = (i & 7) << 2;
            float4 a4 = *(const float4*)(F + (size_t)(bm + r) * Dd + k0 + c);
            sA[r][c + 0] = a4.x; sA[r][c + 1] = a4.y; sA[r][c + 2] = a4.z; sA[r][c + 3] = a4.w;
            float4 b4 = *(const float4*)(F + (size_t)(bn + r) * Dd + k0 + c);
            sB[r][c + 0] = b4.x; sB[r][c + 1] = b4.y; sB[r][c + 2] = b4.z; sB[r][c + 3] = b4.w;
        }
        __syncthreads();
        #pragma unroll
        for (int k = 0; k < 32; k++) {
            float a0 = sA[tm + 0][k], a1 = sA[tm + 1][k];
            float a2 = sA[tm + 2][k], a3 = sA[tm + 3][k];
            float b0 = sB[tn + 0][k], b1 = sB[tn + 1][k];
            float b2 = sB[tn + 2][k], b3 = sB[tn + 3][k];
            acc[0][0] += a0 * b0; acc[0][1] += a0 * b1; acc[0][2] += a0 * b2; acc[0][3] += a0 * b3;
            acc[1][0] += a1 * b0; acc[1][1] += a1 * b1; acc[1][2] += a1 * b2; acc[1][3] += a1 * b3;
            acc[2][0] += a2 * b0; acc[2][1] += a2 * b1; acc[2][2] += a2 * b2; acc[2][3] += a2 * b3;
            acc[3][0] += a3 * b0; acc[3][1] += a3 * b1; acc[3][2] += a3 * b2; acc[3][3] += a3 * b3;
        }
        __syncthreads();
    }
    #pragma unroll
    for (int i = 0; i < 4; i++) {
        float4 v;
        v.x = 1.f / (1.f + __expf(-acc[i][0]));
        v.y = 1.f / (1.f + __expf(-acc[i][1]));
        v.z = 1.f / (1.f + __expf(-acc[i][2]));
        v.w = 1.f / (1.f + __expf(-acc[i][3]));
        *(float4*)(OUT + (size_t)(bm + tm + i) * Tt + bn + tn) = v;
    }
}

// ---------------- launch ----------------
extern "C" void kernel_launch(void* const* d_in, const int* in_sizes, int n_in,
                              void* d_out, int out_size)
{
    const float* x1 = (const float*)d_in[0];
    const float* x2 = (const float*)d_in[1];
    const int*   ei1 = (const int*)d_in[2];
    const int*   ei2 = (const int*)d_in[3];
    const float* Wk[2] = {(const float*)d_in[4],  (const float*)d_in[13]};
    const float* bk[2] = {(const float*)d_in[5],  (const float*)d_in[14]};
    const float* Wq[2] = {(const float*)d_in[6],  (const float*)d_in[15]};
    const float* bq[2] = {(const float*)d_in[7],  (const float*)d_in[16]};
    const float* Wv[2] = {(const float*)d_in[8],  (const float*)d_in[17]};
    const float* bv[2] = {(const float*)d_in[9],  (const float*)d_in[18]};
    const float* Wl[2] = {(const float*)d_in[10], (const float*)d_in[19]};
    const float* bl[2] = {(const float*)d_in[11], (const float*)d_in[20]};
    const float* Wr[2] = {(const float*)d_in[12], (const float*)d_in[21]};

    float *pX, *pH, *pk, *pv, *pq, *pao, *pfeats, *pagg;
    int* pdeg;
    cudaGetSymbolAddress((void**)&pX, g_X);
    cudaGetSymbolAddress((void**)&pH, g_H);
    cudaGetSymbolAddress((void**)&pk, g_k);
    cudaGetSymbolAddress((void**)&pv, g_v);
    cudaGetSymbolAddress((void**)&pq, g_q);
    cudaGetSymbolAddress((void**)&pao, g_ao);
    cudaGetSymbolAddress((void**)&pfeats, g_feats);
    cudaGetSymbolAddress((void**)&pagg, g_agg);
    cudaGetSymbolAddress((void**)&pdeg, g_deg);

    cudaFuncSetAttribute(attn_kernel, cudaFuncAttributeMaxDynamicSharedMemorySize, ATTN_SMEM);

    cudaMemcpyAsync(pX, x1, (size_t)Nn * Dd * sizeof(float), cudaMemcpyDeviceToDevice);
    cudaMemcpyAsync(pX + (size_t)Nn * Dd, x2, (size_t)Nn * Dd * sizeof(float),
                    cudaMemcpyDeviceToDevice);

    dim3 gM(Tt / 64, Dd / 64);   // (128, 2)
    for (int L = 0; L < 2; L++) {
        const float* Xc = L ? pH : pX;
        float*       Ho = L ? pX : pH;

        gemm_kernel<<<gM, 256>>>(Xc, Wk[L], bk[L], pk, Tt, Dd, Dd, 0, 0);
        gemm_kernel<<<gM, 256>>>(Xc, Wv[L], bv[L], pv, Tt, Dd, Dd, 0, 0);
        gemm_kernel<<<gM, 256>>>(Xc, Wq[L], bq[L], pq, Tt, Dd, Dd, 0, 0);

        attn_kernel<<<dim3(Nn / 64, 2), 256, ATTN_SMEM>>>(pq, pk, pv, pao);

        feats_kernel<<<(Tt * 32) / 256, 256>>>(Xc, pao, pfeats);

        cudaMemsetAsync(pagg, 0, (size_t)Tt * 256 * sizeof(float));
        cudaMemsetAsync(pdeg, 0, Tt * sizeof(int));
        edge_kernel<<<dim3(2048, 2), 256>>>(ei1, ei2, pfeats, pagg, pdeg);
        mean_kernel<<<(Tt * 64) / 256, 256>>>(pagg, pdeg);

        gemm_kernel<<<gM, 256>>>(pagg, Wl[L], bl[L], Ho, Tt, Dd, 256, 0, 0);
        gemm_kernel<<<gM, 256>>>(pfeats, Wr[L], nullptr, Ho, Tt, Dd, 256, 1, L == 0 ? 1 : 0);
    }

    final_kernel<<<dim3(Tt / 64, Tt / 64), 256>>>(pX, (float*)d_out);
}

// round 3
// speedup vs baseline: 2.6703x; 2.6703x over previous
#include <cuda_runtime.h>
#include <math.h>
#include <stdint.h>

#define Nn 4096
#define Ee 65536
#define Dd 128
#define Tt 8192   // 2*Nn

// ---------------- scratch (static device allocations only) ----------------
__device__ float g_X[Tt * Dd];
__device__ float g_H[Tt * Dd];
__device__ float g_k[Tt * Dd];
__device__ float g_v[Tt * Dd];
__device__ float g_q[Tt * Dd];
__device__ float g_ao[Tt * Dd];
__device__ float g_feats[(size_t)Tt * 2 * Dd];
__device__ float g_agg[(size_t)Tt * 2 * Dd];
__device__ int   g_deg[Tt];

// ---------------- tf32 helpers ----------------
__device__ __forceinline__ uint32_t to_tf32(float x) {
    uint32_t r;
    asm("cvt.rna.tf32.f32 %0, %1;" : "=r"(r) : "f"(x));
    return r;
}
__device__ __forceinline__ float to_tf32f(float x) {
    return __uint_as_float(to_tf32(x));
}

__device__ __forceinline__ void mma_tf32(float* d, const uint32_t* a, uint32_t b0, uint32_t b1) {
    asm volatile(
        "mma.sync.aligned.m16n8k8.row.col.f32.tf32.tf32.f32 "
        "{%0,%1,%2,%3}, {%4,%5,%6,%7}, {%8,%9}, {%0,%1,%2,%3};\n"
        : "+f"(d[0]), "+f"(d[1]), "+f"(d[2]), "+f"(d[3])
        : "r"(a[0]), "r"(a[1]), "r"(a[2]), "r"(a[3]), "r"(b0), "r"(b1));
}

// ---------------- generic fp32 GEMM: C = act( [C +] A@B + bias ) ----------------
__global__ void gemm_kernel(const float* __restrict__ A, const float* __restrict__ B,
                            const float* __restrict__ bias, float* __restrict__ C,
                            int M, int N, int K, int accum, int relu)
{
    __shared__ float sA[64][20];
    __shared__ float sB[16][64];
    const int tid = threadIdx.x;
    const int tm = (tid >> 4) << 2;
    const int tn = (tid & 15) << 2;
    const int bm = blockIdx.x * 64;
    const int bn = blockIdx.y * 64;
    float acc[4][4] = {};

    for (int k0 = 0; k0 < K; k0 += 16) {
        {
            int r = tid >> 2;
            int c = (tid & 3) << 2;
            float4 av = *(const float4*)(A + (size_t)(bm + r) * K + k0 + c);
            *(float4*)&sA[r][c] = av;
        }
        {
            int rb = tid >> 4;
            int cb = (tid & 15) << 2;
            float4 bv = *(const float4*)(B + (size_t)(k0 + rb) * N + bn + cb);
            *(float4*)&sB[rb][cb] = bv;
        }
        __syncthreads();
        #pragma unroll
        for (int k = 0; k < 16; k++) {
            float a0 = sA[tm + 0][k], a1 = sA[tm + 1][k];
            float a2 = sA[tm + 2][k], a3 = sA[tm + 3][k];
            float4 b4 = *(float4*)&sB[k][tn];
            acc[0][0] += a0 * b4.x; acc[0][1] += a0 * b4.y; acc[0][2] += a0 * b4.z; acc[0][3] += a0 * b4.w;
            acc[1][0] += a1 * b4.x; acc[1][1] += a1 * b4.y; acc[1][2] += a1 * b4.z; acc[1][3] += a1 * b4.w;
            acc[2][0] += a2 * b4.x; acc[2][1] += a2 * b4.y; acc[2][2] += a2 * b4.z; acc[2][3] += a2 * b4.w;
            acc[3][0] += a3 * b4.x; acc[3][1] += a3 * b4.y; acc[3][2] += a3 * b4.z; acc[3][3] += a3 * b4.w;
        }
        __syncthreads();
    }

    float4 b4 = make_float4(0.f, 0.f, 0.f, 0.f);
    if (bias) b4 = *(const float4*)(bias + bn + tn);
    #pragma unroll
    for (int i = 0; i < 4; i++) {
        size_t off = (size_t)(bm + tm + i) * N + bn + tn;
        float4 v = make_float4(acc[i][0] + b4.x, acc[i][1] + b4.y,
                               acc[i][2] + b4.z, acc[i][3] + b4.w);
        if (accum) {
            float4 c4 = *(const float4*)(C + off);
            v.x += c4.x; v.y += c4.y; v.z += c4.z; v.w += c4.w;
        }
        if (relu) {
            v.x = fmaxf(v.x, 0.f); v.y = fmaxf(v.y, 0.f);
            v.z = fmaxf(v.z, 0.f); v.w = fmaxf(v.w, 0.f);
        }
        *(float4*)(C + off) = v;
    }
}

// ---------------- flash attention, tf32 mma, online softmax ----------------
// Block: 128 threads (4 warps). Q tile 64 rows (16/warp). KV tile 64. d=128.
// grid: (Nn/64, 2 graphs).
#define SK_STRIDE 132
#define SV_STRIDE 136
#define SP_STRIDE 68
#define ATTN_SMEM ((64 * SK_STRIDE + 64 * SV_STRIDE + 64 * SP_STRIDE) * 4)

__global__ void __launch_bounds__(128)
attn_kernel(const float* __restrict__ Q, const float* __restrict__ K,
            const float* __restrict__ V, float* __restrict__ O)
{
    extern __shared__ float sm[];
    float* sK = sm;                        // 64 x 132
    float* sV = sm + 64 * SK_STRIDE;       // 64 x 136
    float* sP = sV + 64 * SV_STRIDE;       // 64 x 68
    const int tid  = threadIdx.x;
    const int warp = tid >> 5;
    const int lane = tid & 31;
    const int g    = lane >> 2;   // 0..7
    const int tig  = lane & 3;    // 0..3
    const int qr   = warp * 16;   // warp's q-row base within tile
    const int qbase = blockIdx.y * Nn + blockIdx.x * 64;
    const float inv_scale = 0.08838834764831845f;

    // stage Q tile into sK (tf32), then each thread grabs its A fragments
    for (int i = tid; i < 64 * 32; i += 128) {
        int r = i >> 5, c = (i & 31) << 2;
        float4 v4 = *(const float4*)(Q + (size_t)(qbase + r) * Dd + c);
        float* p = sK + r * SK_STRIDE + c;
        p[0] = to_tf32f(v4.x); p[1] = to_tf32f(v4.y);
        p[2] = to_tf32f(v4.z); p[3] = to_tf32f(v4.w);
    }
    __syncthreads();

    uint32_t qa[16][4];
    #pragma unroll
    for (int kk = 0; kk < 16; kk++) {
        const float* base = sK + (qr + g) * SK_STRIDE + 8 * kk + tig;
        qa[kk][0] = __float_as_uint(base[0]);
        qa[kk][1] = __float_as_uint(base[8 * SK_STRIDE]);
        qa[kk][2] = __float_as_uint(base[4]);
        qa[kk][3] = __float_as_uint(base[8 * SK_STRIDE + 4]);
    }
    __syncthreads();

    float o[16][4];
    #pragma unroll
    for (int nt = 0; nt < 16; nt++) { o[nt][0] = o[nt][1] = o[nt][2] = o[nt][3] = 0.f; }
    float m0 = -1e30f, m1 = -1e30f, l0 = 0.f, l1 = 0.f;

    for (int n0 = 0; n0 < Tt; n0 += 64) {
        // load K, V tiles (tf32)
        for (int i = tid; i < 64 * 32; i += 128) {
            int r = i >> 5, c = (i & 31) << 2;
            float4 kv = *(const float4*)(K + (size_t)(n0 + r) * Dd + c);
            float* pk = sK + r * SK_STRIDE + c;
            pk[0] = to_tf32f(kv.x); pk[1] = to_tf32f(kv.y);
            pk[2] = to_tf32f(kv.z); pk[3] = to_tf32f(kv.w);
            float4 vv = *(const float4*)(V + (size_t)(n0 + r) * Dd + c);
            float* pv = sV + r * SV_STRIDE + c;
            pv[0] = to_tf32f(vv.x); pv[1] = to_tf32f(vv.y);
            pv[2] = to_tf32f(vv.z); pv[3] = to_tf32f(vv.w);
        }
        __syncthreads();

        // S = Q @ K^T  (A = qa regs, B from sK; conflict-free)
        float s[8][4];
        #pragma unroll
        for (int nt = 0; nt < 8; nt++) { s[nt][0] = s[nt][1] = s[nt][2] = s[nt][3] = 0.f; }
        #pragma unroll
        for (int kk = 0; kk < 16; kk++) {
            #pragma unroll
            for (int nt = 0; nt < 8; nt++) {
                const float* bp = sK + (nt * 8 + g) * SK_STRIDE + 8 * kk + tig;
                mma_tf32(s[nt], qa[kk], __float_as_uint(bp[0]), __float_as_uint(bp[4]));
            }
        }

        // online softmax on fragments
        float tmax0 = -1e30f, tmax1 = -1e30f;
        #pragma unroll
        for (int nt = 0; nt < 8; nt++) {
            s[nt][0] *= inv_scale; s[nt][1] *= inv_scale;
            s[nt][2] *= inv_scale; s[nt][3] *= inv_scale;
            tmax0 = fmaxf(tmax0, fmaxf(s[nt][0], s[nt][1]));
            tmax1 = fmaxf(tmax1, fmaxf(s[nt][2], s[nt][3]));
        }
        tmax0 = fmaxf(tmax0, __shfl_xor_sync(0xffffffffu, tmax0, 1));
        tmax0 = fmaxf(tmax0, __shfl_xor_sync(0xffffffffu, tmax0, 2));
        tmax1 = fmaxf(tmax1, __shfl_xor_sync(0xffffffffu, tmax1, 1));
        tmax1 = fmaxf(tmax1, __shfl_xor_sync(0xffffffffu, tmax1, 2));

        float nm0 = fmaxf(m0, tmax0), nm1 = fmaxf(m1, tmax1);
        float cr0 = __expf(m0 - nm0), cr1 = __expf(m1 - nm1);
        float ls0 = 0.f, ls1 = 0.f;
        #pragma unroll
        for (int nt = 0; nt < 8; nt++) {
            float p0 = __expf(s[nt][0] - nm0), p1 = __expf(s[nt][1] - nm0);
            float p2 = __expf(s[nt][2] - nm1), p3 = __expf(s[nt][3] - nm1);
            ls0 += p0 + p1; ls1 += p2 + p3;
            *(float2*)(sP + (qr + g) * SP_STRIDE + nt * 8 + 2 * tig) =
                make_float2(to_tf32f(p0), to_tf32f(p1));
            *(float2*)(sP + (qr + g + 8) * SP_STRIDE + nt * 8 + 2 * tig) =
                make_float2(to_tf32f(p2), to_tf32f(p3));
        }
        ls0 += __shfl_xor_sync(0xffffffffu, ls0, 1);
        ls0 += __shfl_xor_sync(0xffffffffu, ls0, 2);
        ls1 += __shfl_xor_sync(0xffffffffu, ls1, 1);
        ls1 += __shfl_xor_sync(0xffffffffu, ls1, 2);
        l0 = l0 * cr0 + ls0;
        l1 = l1 * cr1 + ls1;
        m0 = nm0; m1 = nm1;

        #pragma unroll
        for (int nt = 0; nt < 16; nt++) {
            o[nt][0] *= cr0; o[nt][1] *= cr0;
            o[nt][2] *= cr1; o[nt][3] *= cr1;
        }
        __syncwarp();   // sP rows are warp-private: order STS -> LDS within warp

        // O += P @ V   (A from sP, B from sV; conflict-free)
        #pragma unroll
        for (int kk = 0; kk < 8; kk++) {
            uint32_t a[4];
            const float* ap = sP + (qr + g) * SP_STRIDE + 8 * kk + tig;
            a[0] = __float_as_uint(ap[0]);
            a[1] = __float_as_uint(ap[8 * SP_STRIDE]);
            a[2] = __float_as_uint(ap[4]);
            a[3] = __float_as_uint(ap[8 * SP_STRIDE + 4]);
            #pragma unroll
            for (int nt = 0; nt < 16; nt++) {
                const float* bp = sV + (8 * kk + tig) * SV_STRIDE + nt * 8 + g;
                mma_tf32(o[nt], a, __float_as_uint(bp[0]), __float_as_uint(bp[4 * SV_STRIDE]));
            }
        }
        __syncthreads();   // all warps done with sK/sV before next tile load
    }

    float il0 = 1.f / l0, il1 = 1.f / l1;
    #pragma unroll
    for (int nt = 0; nt < 16; nt++) {
        float* p = O + (size_t)(qbase + qr + g) * Dd + nt * 8 + 2 * tig;
        *(float2*)p = make_float2(o[nt][0] * il0, o[nt][1] * il0);
        *(float2*)(p + 8 * Dd) = make_float2(o[nt][2] * il1, o[nt][3] * il1);
    }
}

// ---------------- feats = [X | X - attn_out] ----------------
__global__ void feats_kernel(const float* __restrict__ X, const float* __restrict__ AO,
                             float* __restrict__ F)
{
    int i = blockIdx.x * blockDim.x + threadIdx.x;
    if (i >= Tt * 32) return;
    int r = i >> 5, c = i & 31;
    float4 x = ((const float4*)X)[(size_t)r * 32 + c];
    float4 o = ((const float4*)AO)[(size_t)r * 32 + c];
    ((float4*)F)[(size_t)r * 64 + c] = x;
    ((float4*)F)[(size_t)r * 64 + 32 + c] =
        make_float4(x.x - o.x, x.y - o.y, x.z - o.z, x.w - o.w);
}

// ---------------- edge scatter ----------------
__global__ void edge_kernel(const int* __restrict__ ei1, const int* __restrict__ ei2,
                            const float* __restrict__ F, float* __restrict__ AGG,
                            int* __restrict__ DEG)
{
    const int g = blockIdx.y;
    const int* ei = g ? ei2 : ei1;
    const int base = g * Nn;
    for (int e = blockIdx.x; e < Ee; e += gridDim.x) {
        int src = ei[e] + base;
        int dst = ei[Ee + e] + base;
        atomicAdd(&AGG[(size_t)dst * 256 + threadIdx.x], F[(size_t)src * 256 + threadIdx.x]);
        if (threadIdx.x == 0) atomicAdd(&DEG[dst], 1);
    }
}

// ---------------- mean = agg / max(deg,1) ----------------
__global__ void mean_kernel(float* __restrict__ AGG, const int* __restrict__ DEG)
{
    int i = blockIdx.x * blockDim.x + threadIdx.x;
    if (i >= Tt * 64) return;
    int r = i >> 6;
    int d = DEG[r];
    float s = 1.f / (float)(d > 1 ? d : 1);
    float4 v = ((float4*)AGG)[i];
    v.x *= s; v.y *= s; v.z *= s; v.w *= s;
    ((float4*)AGG)[i] = v;
}

// ---------------- final: OUT = sigmoid(F @ F^T), tf32 mma ----------------
// Block 256 threads (8 warps), tile 128x128, K chunked by 64. grid (64,64).
#define FS_STRIDE 68
#define FINAL_SMEM (2 * 128 * FS_STRIDE * 4)

__global__ void __launch_bounds__(256)
final_kernel(const float* __restrict__ F, float* __restrict__ OUT)
{
    extern __shared__ float sm[];
    float* sA = sm;                    // 128 x 68
    float* sB = sm + 128 * FS_STRIDE;  // 128 x 68
    const int tid  = threadIdx.x;
    const int warp = tid >> 5;
    const int lane = tid & 31;
    const int g    = lane >> 2;
    const int tig  = lane & 3;
    const int wm   = warp >> 1;   // 0..3 -> 32 rows each
    const int wn   = warp & 1;    // 0..1 -> 64 cols each
    const int bm = blockIdx.x * 128;
    const int bn = blockIdx.y * 128;

    float c[2][8][4];
    #pragma unroll
    for (int mt = 0; mt < 2; mt++)
        #pragma unroll
        for (int nt = 0; nt < 8; nt++)
            c[mt][nt][0] = c[mt][nt][1] = c[mt][nt][2] = c[mt][nt][3] = 0.f;

    for (int k0 = 0; k0 < Dd; k0 += 64) {
        for (int i = tid; i < 128 * 16; i += 256) {
            int r = i >> 4, cc = (i & 15) << 2;
            float4 a4 = *(const float4*)(F + (size_t)(bm + r) * Dd + k0 + cc);
            float* pa = sA + r * FS_STRIDE + cc;
            pa[0] = to_tf32f(a4.x); pa[1] = to_tf32f(a4.y);
            pa[2] = to_tf32f(a4.z); pa[3] = to_tf32f(a4.w);
            float4 b4 = *(const float4*)(F + (size_t)(bn + r) * Dd + k0 + cc);
            float* pb = sB + r * FS_STRIDE + cc;
            pb[0] = to_tf32f(b4.x); pb[1] = to_tf32f(b4.y);
            pb[2] = to_tf32f(b4.z); pb[3] = to_tf32f(b4.w);
        }
        __syncthreads();

        #pragma unroll
        for (int kk = 0; kk < 8; kk++) {
            uint32_t a[2][4];
            #pragma unroll
            for (int mt = 0; mt < 2; mt++) {
                const float* ap = sA + (wm * 32 + mt * 16 + g) * FS_STRIDE + 8 * kk + tig;
                a[mt][0] = __float_as_uint(ap[0]);
                a[mt][1] = __float_as_uint(ap[8 * FS_STRIDE]);
                a[mt][2] = __float_as_uint(ap[4]);
                a[mt][3] = __float_as_uint(ap[8 * FS_STRIDE + 4]);
            }
            #pragma unroll
            for (int nt = 0; nt < 8; nt++) {
                const float* bp = sB + (wn * 64 + nt * 8 + g) * FS_STRIDE + 8 * kk + tig;
                uint32_t b0 = __float_as_uint(bp[0]);
                uint32_t b1 = __float_as_uint(bp[4]);
                mma_tf32(c[0][nt], a[0], b0, b1);
                mma_tf32(c[1][nt], a[1], b0, b1);
            }
        }
        __syncthreads();
    }

    #pragma unroll
    for (int mt = 0; mt < 2; mt++) {
        #pragma unroll
        for (int nt = 0; nt < 8; nt++) {
            size_t row0 = (size_t)(bm + wm * 32 + mt * 16 + g);
            size_t col  = (size_t)(bn + wn * 64 + nt * 8 + 2 * tig);
            float* p0 = OUT + row0 * Tt + col;
            float* p1 = OUT + (row0 + 8) * Tt + col;
            *(float2*)p0 = make_float2(1.f / (1.f + __expf(-c[mt][nt][0])),
                                       1.f / (1.f + __expf(-c[mt][nt][1])));
            *(float2*)p1 = make_float2(1.f / (1.f + __expf(-c[mt][nt][2])),
                                       1.f / (1.f + __expf(-c[mt][nt][3])));
        }
    }
}

// ---------------- launch ----------------
extern "C" void kernel_launch(void* const* d_in, const int* in_sizes, int n_in,
                              void* d_out, int out_size)
{
    const float* x1 = (const float*)d_in[0];
    const float* x2 = (const float*)d_in[1];
    const int*   ei1 = (const int*)d_in[2];
    const int*   ei2 = (const int*)d_in[3];
    const float* Wk[2] = {(const float*)d_in[4],  (const float*)d_in[13]};
    const float* bk[2] = {(const float*)d_in[5],  (const float*)d_in[14]};
    const float* Wq[2] = {(const float*)d_in[6],  (const float*)d_in[15]};
    const float* bq[2] = {(const float*)d_in[7],  (const float*)d_in[16]};
    const float* Wv[2] = {(const float*)d_in[8],  (const float*)d_in[17]};
    const float* bv[2] = {(const float*)d_in[9],  (const float*)d_in[18]};
    const float* Wl[2] = {(const float*)d_in[10], (const float*)d_in[19]};
    const float* bl[2] = {(const float*)d_in[11], (const float*)d_in[20]};
    const float* Wr[2] = {(const float*)d_in[12], (const float*)d_in[21]};

    float *pX, *pH, *pk, *pv, *pq, *pao, *pfeats, *pagg;
    int* pdeg;
    cudaGetSymbolAddress((void**)&pX, g_X);
    cudaGetSymbolAddress((void**)&pH, g_H);
    cudaGetSymbolAddress((void**)&pk, g_k);
    cudaGetSymbolAddress((void**)&pv, g_v);
    cudaGetSymbolAddress((void**)&pq, g_q);
    cudaGetSymbolAddress((void**)&pao, g_ao);
    cudaGetSymbolAddress((void**)&pfeats, g_feats);
    cudaGetSymbolAddress((void**)&pagg, g_agg);
    cudaGetSymbolAddress((void**)&pdeg, g_deg);

    cudaFuncSetAttribute(attn_kernel, cudaFuncAttributeMaxDynamicSharedMemorySize, ATTN_SMEM);
    cudaFuncSetAttribute(final_kernel, cudaFuncAttributeMaxDynamicSharedMemorySize, FINAL_SMEM);

    cudaMemcpyAsync(pX, x1, (size_t)Nn * Dd * sizeof(float), cudaMemcpyDeviceToDevice);
    cudaMemcpyAsync(pX + (size_t)Nn * Dd, x2, (size_t)Nn * Dd * sizeof(float),
                    cudaMemcpyDeviceToDevice);

    dim3 gM(Tt / 64, Dd / 64);   // (128, 2)
    for (int L = 0; L < 2; L++) {
        const float* Xc = L ? pH : pX;
        float*       Ho = L ? pX : pH;

        gemm_kernel<<<gM, 256>>>(Xc, Wk[L], bk[L], pk, Tt, Dd, Dd, 0, 0);
        gemm_kernel<<<gM, 256>>>(Xc, Wv[L], bv[L], pv, Tt, Dd, Dd, 0, 0);
        gemm_kernel<<<gM, 256>>>(Xc, Wq[L], bq[L], pq, Tt, Dd, Dd, 0, 0);

        attn_kernel<<<dim3(Nn / 64, 2), 128, ATTN_SMEM>>>(pq, pk, pv, pao);

        feats_kernel<<<(Tt * 32) / 256, 256>>>(Xc, pao, pfeats);

        cudaMemsetAsync(pagg, 0, (size_t)Tt * 256 * sizeof(float));
        cudaMemsetAsync(pdeg, 0, Tt * sizeof(int));
        edge_kernel<<<dim3(2048, 2), 256>>>(ei1, ei2, pfeats, pagg, pdeg);
        mean_kernel<<<(Tt * 64) / 256, 256>>>(pagg, pdeg);

        gemm_kernel<<<gM, 256>>>(pagg, Wl[L], bl[L], Ho, Tt, Dd, 256, 0, 0);
        gemm_kernel<<<gM, 256>>>(pfeats, Wr[L], nullptr, Ho, Tt, Dd, 256, 1, L == 0 ? 1 : 0);
    }

    final_kernel<<<dim3(Tt / 128, Tt / 128), 256, FINAL_SMEM>>>(pX, (float*)d_out);
}

// round 4
// speedup vs baseline: 3.3734x; 1.2633x over previous
#include <cuda_runtime.h>
#include <math.h>
#include <stdint.h>

#define Nn 4096
#define Ee 65536
#define Dd 128
#define Tt 8192   // 2*Nn
#define NSPLIT 8
#define KVCHUNK (Tt / NSPLIT)   // 1024

// ---------------- scratch (static device allocations only) ----------------
__device__ float g_X[Tt * Dd];
__device__ float g_H[Tt * Dd];
__device__ float g_k[Tt * Dd];
__device__ float g_v[Tt * Dd];
__device__ float g_q[Tt * Dd];
__device__ float g_ao[Tt * Dd];
__device__ float g_feats[(size_t)Tt * 2 * Dd];
__device__ float g_agg[(size_t)Tt * 2 * Dd];
__device__ int   g_deg[Tt];
__device__ float g_po[(size_t)NSPLIT * Tt * Dd];   // split partial O (unnormalized)
__device__ float g_pm[NSPLIT * Tt];                // split row max
__device__ float g_pl[NSPLIT * Tt];                // split row sum

// ---------------- tf32 helpers ----------------
__device__ __forceinline__ uint32_t to_tf32(float x) {
    uint32_t r;
    asm("cvt.rna.tf32.f32 %0, %1;" : "=r"(r) : "f"(x));
    return r;
}
__device__ __forceinline__ float to_tf32f(float x) {
    return __uint_as_float(to_tf32(x));
}

__device__ __forceinline__ void mma_tf32(float* d, const uint32_t* a, uint32_t b0, uint32_t b1) {
    asm volatile(
        "mma.sync.aligned.m16n8k8.row.col.f32.tf32.tf32.f32 "
        "{%0,%1,%2,%3}, {%4,%5,%6,%7}, {%8,%9}, {%0,%1,%2,%3};\n"
        : "+f"(d[0]), "+f"(d[1]), "+f"(d[2]), "+f"(d[3])
        : "r"(a[0]), "r"(a[1]), "r"(a[2]), "r"(a[3]), "r"(b0), "r"(b1));
}

// ---------------- generic fp32 GEMM: C = act( [C +] A@B + bias ) ----------------
__global__ void gemm_kernel(const float* __restrict__ A, const float* __restrict__ B,
                            const float* __restrict__ bias, float* __restrict__ C,
                            int M, int N, int K, int accum, int relu)
{
    __shared__ float sA[64][20];
    __shared__ float sB[16][64];
    const int tid = threadIdx.x;
    const int tm = (tid >> 4) << 2;
    const int tn = (tid & 15) << 2;
    const int bm = blockIdx.x * 64;
    const int bn = blockIdx.y * 64;
    float acc[4][4] = {};

    for (int k0 = 0; k0 < K; k0 += 16) {
        {
            int r = tid >> 2;
            int c = (tid & 3) << 2;
            float4 av = *(const float4*)(A + (size_t)(bm + r) * K + k0 + c);
            *(float4*)&sA[r][c] = av;
        }
        {
            int rb = tid >> 4;
            int cb = (tid & 15) << 2;
            float4 bv = *(const float4*)(B + (size_t)(k0 + rb) * N + bn + cb);
            *(float4*)&sB[rb][cb] = bv;
        }
        __syncthreads();
        #pragma unroll
        for (int k = 0; k < 16; k++) {
            float a0 = sA[tm + 0][k], a1 = sA[tm + 1][k];
            float a2 = sA[tm + 2][k], a3 = sA[tm + 3][k];
            float4 b4 = *(float4*)&sB[k][tn];
            acc[0][0] += a0 * b4.x; acc[0][1] += a0 * b4.y; acc[0][2] += a0 * b4.z; acc[0][3] += a0 * b4.w;
            acc[1][0] += a1 * b4.x; acc[1][1] += a1 * b4.y; acc[1][2] += a1 * b4.z; acc[1][3] += a1 * b4.w;
            acc[2][0] += a2 * b4.x; acc[2][1] += a2 * b4.y; acc[2][2] += a2 * b4.z; acc[2][3] += a2 * b4.w;
            acc[3][0] += a3 * b4.x; acc[3][1] += a3 * b4.y; acc[3][2] += a3 * b4.z; acc[3][3] += a3 * b4.w;
        }
        __syncthreads();
    }

    float4 b4 = make_float4(0.f, 0.f, 0.f, 0.f);
    if (bias) b4 = *(const float4*)(bias + bn + tn);
    #pragma unroll
    for (int i = 0; i < 4; i++) {
        size_t off = (size_t)(bm + tm + i) * N + bn + tn;
        float4 v = make_float4(acc[i][0] + b4.x, acc[i][1] + b4.y,
                               acc[i][2] + b4.z, acc[i][3] + b4.w);
        if (accum) {
            float4 c4 = *(const float4*)(C + off);
            v.x += c4.x; v.y += c4.y; v.z += c4.z; v.w += c4.w;
        }
        if (relu) {
            v.x = fmaxf(v.x, 0.f); v.y = fmaxf(v.y, 0.f);
            v.z = fmaxf(v.z, 0.f); v.w = fmaxf(v.w, 0.f);
        }
        *(float4*)(C + off) = v;
    }
}

// ---------------- fused QKV projection (3 GEMMs in one launch via z) ----------------
__global__ void gemm_qkv_kernel(const float* __restrict__ A,
                                const float* __restrict__ Wk, const float* __restrict__ bk,
                                const float* __restrict__ Wv, const float* __restrict__ bv,
                                const float* __restrict__ Wq, const float* __restrict__ bq,
                                float* __restrict__ Ck, float* __restrict__ Cv,
                                float* __restrict__ Cq)
{
    const float* B    = blockIdx.z == 0 ? Wk : (blockIdx.z == 1 ? Wv : Wq);
    const float* bias = blockIdx.z == 0 ? bk : (blockIdx.z == 1 ? bv : bq);
    float*       C    = blockIdx.z == 0 ? Ck : (blockIdx.z == 1 ? Cv : Cq);

    __shared__ float sA[64][20];
    __shared__ float sB[16][64];
    const int tid = threadIdx.x;
    const int tm = (tid >> 4) << 2;
    const int tn = (tid & 15) << 2;
    const int bm = blockIdx.x * 64;
    const int bn = blockIdx.y * 64;
    float acc[4][4] = {};

    for (int k0 = 0; k0 < Dd; k0 += 16) {
        {
            int r = tid >> 2;
            int c = (tid & 3) << 2;
            *(float4*)&sA[r][c] = *(const float4*)(A + (size_t)(bm + r) * Dd + k0 + c);
        }
        {
            int rb = tid >> 4;
            int cb = (tid & 15) << 2;
            *(float4*)&sB[rb][cb] = *(const float4*)(B + (size_t)(k0 + rb) * Dd + bn + cb);
        }
        __syncthreads();
        #pragma unroll
        for (int k = 0; k < 16; k++) {
            float a0 = sA[tm + 0][k], a1 = sA[tm + 1][k];
            float a2 = sA[tm + 2][k], a3 = sA[tm + 3][k];
            float4 b4 = *(float4*)&sB[k][tn];
            acc[0][0] += a0 * b4.x; acc[0][1] += a0 * b4.y; acc[0][2] += a0 * b4.z; acc[0][3] += a0 * b4.w;
            acc[1][0] += a1 * b4.x; acc[1][1] += a1 * b4.y; acc[1][2] += a1 * b4.z; acc[1][3] += a1 * b4.w;
            acc[2][0] += a2 * b4.x; acc[2][1] += a2 * b4.y; acc[2][2] += a2 * b4.z; acc[2][3] += a2 * b4.w;
            acc[3][0] += a3 * b4.x; acc[3][1] += a3 * b4.y; acc[3][2] += a3 * b4.z; acc[3][3] += a3 * b4.w;
        }
        __syncthreads();
    }

    float4 b4 = *(const float4*)(bias + bn + tn);
    #pragma unroll
    for (int i = 0; i < 4; i++) {
        size_t off = (size_t)(bm + tm + i) * Dd + bn + tn;
        *(float4*)(C + off) = make_float4(acc[i][0] + b4.x, acc[i][1] + b4.y,
                                          acc[i][2] + b4.z, acc[i][3] + b4.w);
    }
}

// ---------------- split-KV flash attention, tf32 mma ----------------
// grid: (Nn/64, 2 graphs, NSPLIT). Block 128 threads (4 warps), 16 q-rows/warp.
// Each block covers KV rows [z*KVCHUNK, (z+1)*KVCHUNK); writes unnormalized
// partial O plus (m, l) per q row.
#define SK_STRIDE 132
#define SV_STRIDE 136
#define SP_STRIDE 68
#define ATTN_SMEM ((64 * SK_STRIDE + 64 * SV_STRIDE + 64 * SP_STRIDE) * 4)

__global__ void __launch_bounds__(128)
attn_split_kernel(const float* __restrict__ Q, const float* __restrict__ K,
                  const float* __restrict__ V, float* __restrict__ PO,
                  float* __restrict__ PM, float* __restrict__ PL)
{
    extern __shared__ float sm[];
    float* sK = sm;
    float* sV = sm + 64 * SK_STRIDE;
    float* sP = sV + 64 * SV_STRIDE;
    const int tid  = threadIdx.x;
    const int warp = tid >> 5;
    const int lane = tid & 31;
    const int g    = lane >> 2;
    const int tig  = lane & 3;
    const int qr   = warp * 16;
    const int qbase = blockIdx.y * Nn + blockIdx.x * 64;
    const int kv0   = blockIdx.z * KVCHUNK;
    const float inv_scale = 0.08838834764831845f;

    // stage Q tile into sK (tf32), each thread grabs its A fragments
    for (int i = tid; i < 64 * 32; i += 128) {
        int r = i >> 5, c = (i & 31) << 2;
        float4 v4 = *(const float4*)(Q + (size_t)(qbase + r) * Dd + c);
        float* p = sK + r * SK_STRIDE + c;
        p[0] = to_tf32f(v4.x); p[1] = to_tf32f(v4.y);
        p[2] = to_tf32f(v4.z); p[3] = to_tf32f(v4.w);
    }
    __syncthreads();

    uint32_t qa[16][4];
    #pragma unroll
    for (int kk = 0; kk < 16; kk++) {
        const float* base = sK + (qr + g) * SK_STRIDE + 8 * kk + tig;
        qa[kk][0] = __float_as_uint(base[0]);
        qa[kk][1] = __float_as_uint(base[8 * SK_STRIDE]);
        qa[kk][2] = __float_as_uint(base[4]);
        qa[kk][3] = __float_as_uint(base[8 * SK_STRIDE + 4]);
    }
    __syncthreads();

    float o[16][4];
    #pragma unroll
    for (int nt = 0; nt < 16; nt++) { o[nt][0] = o[nt][1] = o[nt][2] = o[nt][3] = 0.f; }
    float m0 = -1e30f, m1 = -1e30f, l0 = 0.f, l1 = 0.f;

    for (int n0 = kv0; n0 < kv0 + KVCHUNK; n0 += 64) {
        for (int i = tid; i < 64 * 32; i += 128) {
            int r = i >> 5, c = (i & 31) << 2;
            float4 kv = *(const float4*)(K + (size_t)(n0 + r) * Dd + c);
            float* pk = sK + r * SK_STRIDE + c;
            pk[0] = to_tf32f(kv.x); pk[1] = to_tf32f(kv.y);
            pk[2] = to_tf32f(kv.z); pk[3] = to_tf32f(kv.w);
            float4 vv = *(const float4*)(V + (size_t)(n0 + r) * Dd + c);
            float* pv = sV + r * SV_STRIDE + c;
            pv[0] = to_tf32f(vv.x); pv[1] = to_tf32f(vv.y);
            pv[2] = to_tf32f(vv.z); pv[3] = to_tf32f(vv.w);
        }
        __syncthreads();

        float s[8][4];
        #pragma unroll
        for (int nt = 0; nt < 8; nt++) { s[nt][0] = s[nt][1] = s[nt][2] = s[nt][3] = 0.f; }
        #pragma unroll
        for (int kk = 0; kk < 16; kk++) {
            #pragma unroll
            for (int nt = 0; nt < 8; nt++) {
                const float* bp = sK + (nt * 8 + g) * SK_STRIDE + 8 * kk + tig;
                mma_tf32(s[nt], qa[kk], __float_as_uint(bp[0]), __float_as_uint(bp[4]));
            }
        }

        float tmax0 = -1e30f, tmax1 = -1e30f;
        #pragma unroll
        for (int nt = 0; nt < 8; nt++) {
            s[nt][0] *= inv_scale; s[nt][1] *= inv_scale;
            s[nt][2] *= inv_scale; s[nt][3] *= inv_scale;
            tmax0 = fmaxf(tmax0, fmaxf(s[nt][0], s[nt][1]));
            tmax1 = fmaxf(tmax1, fmaxf(s[nt][2], s[nt][3]));
        }
        tmax0 = fmaxf(tmax0, __shfl_xor_sync(0xffffffffu, tmax0, 1));
        tmax0 = fmaxf(tmax0, __shfl_xor_sync(0xffffffffu, tmax0, 2));
        tmax1 = fmaxf(tmax1, __shfl_xor_sync(0xffffffffu, tmax1, 1));
        tmax1 = fmaxf(tmax1, __shfl_xor_sync(0xffffffffu, tmax1, 2));

        float nm0 = fmaxf(m0, tmax0), nm1 = fmaxf(m1, tmax1);
        float cr0 = __expf(m0 - nm0), cr1 = __expf(m1 - nm1);
        float ls0 = 0.f, ls1 = 0.f;
        #pragma unroll
        for (int nt = 0; nt < 8; nt++) {
            float p0 = __expf(s[nt][0] - nm0), p1 = __expf(s[nt][1] - nm0);
            float p2 = __expf(s[nt][2] - nm1), p3 = __expf(s[nt][3] - nm1);
            ls0 += p0 + p1; ls1 += p2 + p3;
            *(float2*)(sP + (qr + g) * SP_STRIDE + nt * 8 + 2 * tig) =
                make_float2(to_tf32f(p0), to_tf32f(p1));
            *(float2*)(sP + (qr + g + 8) * SP_STRIDE + nt * 8 + 2 * tig) =
                make_float2(to_tf32f(p2), to_tf32f(p3));
        }
        ls0 += __shfl_xor_sync(0xffffffffu, ls0, 1);
        ls0 += __shfl_xor_sync(0xffffffffu, ls0, 2);
        ls1 += __shfl_xor_sync(0xffffffffu, ls1, 1);
        ls1 += __shfl_xor_sync(0xffffffffu, ls1, 2);
        l0 = l0 * cr0 + ls0;
        l1 = l1 * cr1 + ls1;
        m0 = nm0; m1 = nm1;

        #pragma unroll
        for (int nt = 0; nt < 16; nt++) {
            o[nt][0] *= cr0; o[nt][1] *= cr0;
            o[nt][2] *= cr1; o[nt][3] *= cr1;
        }
        __syncwarp();

        #pragma unroll
        for (int kk = 0; kk < 8; kk++) {
            uint32_t a[4];
            const float* ap = sP + (qr + g) * SP_STRIDE + 8 * kk + tig;
            a[0] = __float_as_uint(ap[0]);
            a[1] = __float_as_uint(ap[8 * SP_STRIDE]);
            a[2] = __float_as_uint(ap[4]);
            a[3] = __float_as_uint(ap[8 * SP_STRIDE + 4]);
            #pragma unroll
            for (int nt = 0; nt < 16; nt++) {
                const float* bp = sV + (8 * kk + tig) * SV_STRIDE + nt * 8 + g;
                mma_tf32(o[nt], a, __float_as_uint(bp[0]), __float_as_uint(bp[4 * SV_STRIDE]));
            }
        }
        __syncthreads();
    }

    // store unnormalized partial O + (m, l)
    const size_t obase = (size_t)blockIdx.z * Tt;
    #pragma unroll
    for (int nt = 0; nt < 16; nt++) {
        float* p = PO + (obase + qbase + qr + g) * Dd + nt * 8 + 2 * tig;
        *(float2*)p = make_float2(o[nt][0], o[nt][1]);
        *(float2*)(p + 8 * Dd) = make_float2(o[nt][2], o[nt][3]);
    }
    if (tig == 0) {
        PM[obase + qbase + qr + g]     = m0;
        PL[obase + qbase + qr + g]     = l0;
        PM[obase + qbase + qr + g + 8] = m1;
        PL[obase + qbase + qr + g + 8] = l1;
    }
}

// ---------------- combine split partials ----------------
__global__ void attn_combine_kernel(const float* __restrict__ PO,
                                    const float* __restrict__ PM,
                                    const float* __restrict__ PL,
                                    float* __restrict__ O)
{
    int i = blockIdx.x * blockDim.x + threadIdx.x;   // over Tt*32 float4s
    if (i >= Tt * 32) return;
    int r = i >> 5, c = i & 31;

    float m[NSPLIT], M = -1e30f;
    #pragma unroll
    for (int s = 0; s < NSPLIT; s++) {
        m[s] = PM[s * Tt + r];
        M = fmaxf(M, m[s]);
    }
    float w[NSPLIT], L = 0.f;
    #pragma unroll
    for (int s = 0; s < NSPLIT; s++) {
        w[s] = __expf(m[s] - M);
        L += w[s] * PL[s * Tt + r];
    }
    float invL = 1.f / L;

    float4 acc = make_float4(0.f, 0.f, 0.f, 0.f);
    #pragma unroll
    for (int s = 0; s < NSPLIT; s++) {
        float4 v = ((const float4*)PO)[((size_t)s * Tt + r) * 32 + c];
        acc.x += w[s] * v.x; acc.y += w[s] * v.y;
        acc.z += w[s] * v.z; acc.w += w[s] * v.w;
    }
    acc.x *= invL; acc.y *= invL; acc.z *= invL; acc.w *= invL;
    ((float4*)O)[(size_t)r * 32 + c] = acc;
}

// ---------------- feats = [X | X - attn_out] ----------------
__global__ void feats_kernel(const float* __restrict__ X, const float* __restrict__ AO,
                             float* __restrict__ F)
{
    int i = blockIdx.x * blockDim.x + threadIdx.x;
    if (i >= Tt * 32) return;
    int r = i >> 5, c = i & 31;
    float4 x = ((const float4*)X)[(size_t)r * 32 + c];
    float4 o = ((const float4*)AO)[(size_t)r * 32 + c];
    ((float4*)F)[(size_t)r * 64 + c] = x;
    ((float4*)F)[(size_t)r * 64 + 32 + c] =
        make_float4(x.x - o.x, x.y - o.y, x.z - o.z, x.w - o.w);
}

// ---------------- edge scatter ----------------
__global__ void edge_kernel(const int* __restrict__ ei1, const int* __restrict__ ei2,
                            const float* __restrict__ F, float* __restrict__ AGG,
                            int* __restrict__ DEG)
{
    const int g = blockIdx.y;
    const int* ei = g ? ei2 : ei1;
    const int base = g * Nn;
    for (int e = blockIdx.x; e < Ee; e += gridDim.x) {
        int src = ei[e] + base;
        int dst = ei[Ee + e] + base;
        atomicAdd(&AGG[(size_t)dst * 256 + threadIdx.x], F[(size_t)src * 256 + threadIdx.x]);
        if (threadIdx.x == 0) atomicAdd(&DEG[dst], 1);
    }
}

// ---------------- mean = agg / max(deg,1) ----------------
__global__ void mean_kernel(float* __restrict__ AGG, const int* __restrict__ DEG)
{
    int i = blockIdx.x * blockDim.x + threadIdx.x;
    if (i >= Tt * 64) return;
    int r = i >> 6;
    int d = DEG[r];
    float s = 1.f / (float)(d > 1 ? d : 1);
    float4 v = ((float4*)AGG)[i];
    v.x *= s; v.y *= s; v.z *= s; v.w *= s;
    ((float4*)AGG)[i] = v;
}

// ---------------- final: OUT = sigmoid(F @ F^T), tf32 mma ----------------
#define FS_STRIDE 68
#define FINAL_SMEM (2 * 128 * FS_STRIDE * 4)

__global__ void __launch_bounds__(256)
final_kernel(const float* __restrict__ F, float* __restrict__ OUT)
{
    extern __shared__ float sm[];
    float* sA = sm;
    float* sB = sm + 128 * FS_STRIDE;
    const int tid  = threadIdx.x;
    const int warp = tid >> 5;
    const int lane = tid & 31;
    const int g    = lane >> 2;
    const int tig  = lane & 3;
    const int wm   = warp >> 1;
    const int wn   = warp & 1;
    const int bm = blockIdx.x * 128;
    const int bn = blockIdx.y * 128;

    float c[2][8][4];
    #pragma unroll
    for (int mt = 0; mt < 2; mt++)
        #pragma unroll
        for (int nt = 0; nt < 8; nt++)
            c[mt][nt][0] = c[mt][nt][1] = c[mt][nt][2] = c[mt][nt][3] = 0.f;

    for (int k0 = 0; k0 < Dd; k0 += 64) {
        for (int i = tid; i < 128 * 16; i += 256) {
            int r = i >> 4, cc = (i & 15) << 2;
            float4 a4 = *(const float4*)(F + (size_t)(bm + r) * Dd + k0 + cc);
            float* pa = sA + r * FS_STRIDE + cc;
            pa[0] = to_tf32f(a4.x); pa[1] = to_tf32f(a4.y);
            pa[2] = to_tf32f(a4.z); pa[3] = to_tf32f(a4.w);
            float4 b4 = *(const float4*)(F + (size_t)(bn + r) * Dd + k0 + cc);
            float* pb = sB + r * FS_STRIDE + cc;
            pb[0] = to_tf32f(b4.x); pb[1] = to_tf32f(b4.y);
            pb[2] = to_tf32f(b4.z); pb[3] = to_tf32f(b4.w);
        }
        __syncthreads();

        #pragma unroll
        for (int kk = 0; kk < 8; kk++) {
            uint32_t a[2][4];
            #pragma unroll
            for (int mt = 0; mt < 2; mt++) {
                const float* ap = sA + (wm * 32 + mt * 16 + g) * FS_STRIDE + 8 * kk + tig;
                a[mt][0] = __float_as_uint(ap[0]);
                a[mt][1] = __float_as_uint(ap[8 * FS_STRIDE]);
                a[mt][2] = __float_as_uint(ap[4]);
                a[mt][3] = __float_as_uint(ap[8 * FS_STRIDE + 4]);
            }
            #pragma unroll
            for (int nt = 0; nt < 8; nt++) {
                const float* bp = sB + (wn * 64 + nt * 8 + g) * FS_STRIDE + 8 * kk + tig;
                uint32_t b0 = __float_as_uint(bp[0]);
                uint32_t b1 = __float_as_uint(bp[4]);
                mma_tf32(c[0][nt], a[0], b0, b1);
                mma_tf32(c[1][nt], a[1], b0, b1);
            }
        }
        __syncthreads();
    }

    #pragma unroll
    for (int mt = 0; mt < 2; mt++) {
        #pragma unroll
        for (int nt = 0; nt < 8; nt++) {
            size_t row0 = (size_t)(bm + wm * 32 + mt * 16 + g);
            size_t col  = (size_t)(bn + wn * 64 + nt * 8 + 2 * tig);
            float* p0 = OUT + row0 * Tt + col;
            float* p1 = OUT + (row0 + 8) * Tt + col;
            *(float2*)p0 = make_float2(1.f / (1.f + __expf(-c[mt][nt][0])),
                                       1.f / (1.f + __expf(-c[mt][nt][1])));
            *(float2*)p1 = make_float2(1.f / (1.f + __expf(-c[mt][nt][2])),
                                       1.f / (1.f + __expf(-c[mt][nt][3])));
        }
    }
}

// ---------------- launch ----------------
extern "C" void kernel_launch(void* const* d_in, const int* in_sizes, int n_in,
                              void* d_out, int out_size)
{
    const float* x1 = (const float*)d_in[0];
    const float* x2 = (const float*)d_in[1];
    const int*   ei1 = (const int*)d_in[2];
    const int*   ei2 = (const int*)d_in[3];
    const float* Wk[2] = {(const float*)d_in[4],  (const float*)d_in[13]};
    const float* bk[2] = {(const float*)d_in[5],  (const float*)d_in[14]};
    const float* Wq[2] = {(const float*)d_in[6],  (const float*)d_in[15]};
    const float* bq[2] = {(const float*)d_in[7],  (const float*)d_in[16]};
    const float* Wv[2] = {(const float*)d_in[8],  (const float*)d_in[17]};
    const float* bv[2] = {(const float*)d_in[9],  (const float*)d_in[18]};
    const float* Wl[2] = {(const float*)d_in[10], (const float*)d_in[19]};
    const float* bl[2] = {(const float*)d_in[11], (const float*)d_in[20]};
    const float* Wr[2] = {(const float*)d_in[12], (const float*)d_in[21]};

    float *pX, *pH, *pk, *pv, *pq, *pao, *pfeats, *pagg, *ppo, *ppm, *ppl;
    int* pdeg;
    cudaGetSymbolAddress((void**)&pX, g_X);
    cudaGetSymbolAddress((void**)&pH, g_H);
    cudaGetSymbolAddress((void**)&pk, g_k);
    cudaGetSymbolAddress((void**)&pv, g_v);
    cudaGetSymbolAddress((void**)&pq, g_q);
    cudaGetSymbolAddress((void**)&pao, g_ao);
    cudaGetSymbolAddress((void**)&pfeats, g_feats);
    cudaGetSymbolAddress((void**)&pagg, g_agg);
    cudaGetSymbolAddress((void**)&pdeg, g_deg);
    cudaGetSymbolAddress((void**)&ppo, g_po);
    cudaGetSymbolAddress((void**)&ppm, g_pm);
    cudaGetSymbolAddress((void**)&ppl, g_pl);

    cudaFuncSetAttribute(attn_split_kernel, cudaFuncAttributeMaxDynamicSharedMemorySize, ATTN_SMEM);
    cudaFuncSetAttribute(final_kernel, cudaFuncAttributeMaxDynamicSharedMemorySize, FINAL_SMEM);

    cudaMemcpyAsync(pX, x1, (size_t)Nn * Dd * sizeof(float), cudaMemcpyDeviceToDevice);
    cudaMemcpyAsync(pX + (size_t)Nn * Dd, x2, (size_t)Nn * Dd * sizeof(float),
                    cudaMemcpyDeviceToDevice);

    dim3 gM(Tt / 64, Dd / 64);   // (128, 2)
    for (int L = 0; L < 2; L++) {
        const float* Xc = L ? pH : pX;
        float*       Ho = L ? pX : pH;

        gemm_qkv_kernel<<<dim3(Tt / 64, Dd / 64, 3), 256>>>(
            Xc, Wk[L], bk[L], Wv[L], bv[L], Wq[L], bq[L], pk, pv, pq);

        attn_split_kernel<<<dim3(Nn / 64, 2, NSPLIT), 128, ATTN_SMEM>>>(
            pq, pk, pv, ppo, ppm, ppl);
        attn_combine_kernel<<<(Tt * 32) / 256, 256>>>(ppo, ppm, ppl, pao);

        feats_kernel<<<(Tt * 32) / 256, 256>>>(Xc, pao, pfeats);

        cudaMemsetAsync(pagg, 0, (size_t)Tt * 256 * sizeof(float));
        cudaMemsetAsync(pdeg, 0, Tt * sizeof(int));
        edge_kernel<<<dim3(2048, 2), 256>>>(ei1, ei2, pfeats, pagg, pdeg);
        mean_kernel<<<(Tt * 64) / 256, 256>>>(pagg, pdeg);

        gemm_kernel<<<gM, 256>>>(pagg, Wl[L], bl[L], Ho, Tt, Dd, 256, 0, 0);
        gemm_kernel<<<gM, 256>>>(pfeats, Wr[L], nullptr, Ho, Tt, Dd, 256, 1, L == 0 ? 1 : 0);
    }

    final_kernel<<<dim3(Tt / 128, Tt / 128), 256, FINAL_SMEM>>>(pX, (float*)d_out);
}